// round 1
// baseline (speedup 1.0000x reference)
#include <cuda_runtime.h>
#include <cuda_bf16.h>
#include <cstdint>

#define B_    8
#define S_    2048
#define E_    768
#define FF_   3072
#define NQ_   128
#define NTOK  (B_ * S_)

// ---------------- static scratch (device globals; allocation-free) ----------------
__device__ float g_qa [NTOK * E_];                 //  50 MB  cos(proj+theta_rx), [tok][e]
__device__ float g_qaT[B_ * E_ * S_];              //  50 MB  [b][e][s] (for PV gemm B-operand)
__device__ float g_sc [B_ * S_ * S_];              // 134 MB  scores / probs, [b][s][t]
__device__ float g_att[NTOK * E_];                 //  50 MB  attn output
__device__ float g_x1 [NTOK * E_];                 //  50 MB  LN1 output
__device__ float g_qf [NTOK * NQ_];                //   8 MB  cos(x1[:,:NQ]+theta_ry)
__device__ float g_h  [NTOK * FF_];                // 201 MB  relu hidden
__device__ float g_ffn[NTOK * E_];                 //  50 MB  ffn output

// ---------------- small PTX helpers ----------------
__device__ __forceinline__ uint32_t f2tf(float f) {
    uint32_t u;
    asm("cvt.rna.tf32.f32 %0, %1;" : "=r"(u) : "f"(f));
    return u;
}

__device__ __forceinline__ void mma_tf32(float c[4], const uint32_t a[4], const uint32_t b[2]) {
    asm volatile(
        "mma.sync.aligned.m16n8k8.row.col.f32.tf32.tf32.f32 "
        "{%0,%1,%2,%3}, {%4,%5,%6,%7}, {%8,%9}, {%0,%1,%2,%3};\n"
        : "+f"(c[0]), "+f"(c[1]), "+f"(c[2]), "+f"(c[3])
        : "r"(a[0]), "r"(a[1]), "r"(a[2]), "r"(a[3]), "r"(b[0]), "r"(b[1]));
}

__device__ __forceinline__ void cp16(float* dst, const float* src) {
    unsigned d = (unsigned)__cvta_generic_to_shared(dst);
    asm volatile("cp.async.cg.shared.global [%0], [%1], 16;" :: "r"(d), "l"(src));
}

// ---------------- generic TF32 GEMM: C[M,N] = A[M,K] @ B[N,K]^T ----------------
// BM=128, BN=128, BK=16, 256 threads (8 warps as 2x4, warp tile 64x32)
enum { EPI_QA = 0, EPI_SCORES = 1, EPI_NONE = 2, EPI_RELU = 3, EPI_BIAS = 4 };

template <int EPI>
__global__ __launch_bounds__(256)
void gemm_tf32(const float* __restrict__ Aall, const float* __restrict__ Ball,
               float* __restrict__ Call,
               int K, int lda, int ldb, int ldc,
               long bsA, long bsB, long bsC,
               const float* __restrict__ vec)
{
    constexpr int BM = 128, BN = 128, BK = 16, LDS = BK + 4;
    __shared__ float sA[2][BM][LDS];
    __shared__ float sB[2][BN][LDS];

    const float* A  = Aall + (long)blockIdx.z * bsA;
    const float* Bp = Ball + (long)blockIdx.z * bsB;
    float*       C  = Call + (long)blockIdx.z * bsC;

    const int tid  = threadIdx.x;
    const int wid  = tid >> 5, lane = tid & 31;
    const int wm   = wid & 1,  wn   = wid >> 1;      // 2 x 4 warps
    const int r    = lane >> 2, cq  = lane & 3;

    const int row0 = blockIdx.y * BM;
    const int col0 = blockIdx.x * BN;

    float acc[4][4][4];
#pragma unroll
    for (int i = 0; i < 4; i++)
#pragma unroll
        for (int j = 0; j < 4; j++)
#pragma unroll
            for (int k = 0; k < 4; k++) acc[i][j][k] = 0.f;

    const int nk = K / BK;

    auto load_stage = [&](int buf, int kt) {
        const int kbase = kt * BK;
#pragma unroll
        for (int u = 0; u < 2; u++) {
            int c  = tid + u * 256;          // 512 chunks per operand
            int rw = c >> 2, kq = c & 3;
            cp16(&sA[buf][rw][kq * 4], A  + (long)(row0 + rw) * lda + kbase + kq * 4);
            cp16(&sB[buf][rw][kq * 4], Bp + (long)(col0 + rw) * ldb + kbase + kq * 4);
        }
        asm volatile("cp.async.commit_group;");
    };

    load_stage(0, 0);

    for (int kt = 0; kt < nk; kt++) {
        if (kt + 1 < nk) {
            load_stage((kt + 1) & 1, kt + 1);
            asm volatile("cp.async.wait_group 1;");
        } else {
            asm volatile("cp.async.wait_group 0;");
        }
        __syncthreads();
        const int buf = kt & 1;
#pragma unroll
        for (int ks = 0; ks < BK; ks += 8) {
            uint32_t af[4][4], bf[4][2];
#pragma unroll
            for (int i = 0; i < 4; i++) {
                int m = wm * 64 + i * 16;
                af[i][0] = f2tf(sA[buf][m + r    ][ks + cq    ]);
                af[i][1] = f2tf(sA[buf][m + r + 8][ks + cq    ]);
                af[i][2] = f2tf(sA[buf][m + r    ][ks + cq + 4]);
                af[i][3] = f2tf(sA[buf][m + r + 8][ks + cq + 4]);
            }
#pragma unroll
            for (int j = 0; j < 4; j++) {
                int n = wn * 32 + j * 8;
                bf[j][0] = f2tf(sB[buf][n + r][ks + cq    ]);
                bf[j][1] = f2tf(sB[buf][n + r][ks + cq + 4]);
            }
#pragma unroll
            for (int i = 0; i < 4; i++)
#pragma unroll
                for (int j = 0; j < 4; j++)
                    mma_tf32(acc[i][j], af[i], bf[j]);
        }
        __syncthreads();
    }

    // ---------------- epilogue ----------------
    const float scale = 0.35355339059327376f;  // 1/sqrt(8)
#pragma unroll
    for (int i = 0; i < 4; i++) {
        int gm = row0 + wm * 64 + i * 16 + r;
#pragma unroll
        for (int j = 0; j < 4; j++) {
            int gn = col0 + wn * 32 + j * 8 + 2 * cq;
#pragma unroll
            for (int hh = 0; hh < 2; hh++) {
                int gmr = gm + hh * 8;
                float e0 = acc[i][j][hh * 2 + 0];
                float e1 = acc[i][j][hh * 2 + 1];
                if (EPI == EPI_QA) {
                    float q0 = cosf(e0 + vec[gn]);
                    float q1 = cosf(e1 + vec[gn + 1]);
                    *reinterpret_cast<float2*>(&C[(long)gmr * ldc + gn]) = make_float2(q0, q1);
                    int bb = gmr >> 11, ss = gmr & (S_ - 1);
                    g_qaT[((long)bb * E_ + gn    ) * S_ + ss] = q0;
                    g_qaT[((long)bb * E_ + gn + 1) * S_ + ss] = q1;
                } else {
                    if (EPI == EPI_SCORES) { e0 *= scale; e1 *= scale; }
                    else if (EPI == EPI_RELU) {
                        e0 = fmaxf(e0 + vec[gn], 0.f);
                        e1 = fmaxf(e1 + vec[gn + 1], 0.f);
                    } else if (EPI == EPI_BIAS) {
                        e0 += vec[gn];
                        e1 += vec[gn + 1];
                    }
                    *reinterpret_cast<float2*>(&C[(long)gmr * ldc + gn]) = make_float2(e0, e1);
                }
            }
        }
    }
}

// ---------------- block reductions ----------------
__device__ __forceinline__ float blk_sum(float v, float* sh) {
#pragma unroll
    for (int o = 16; o > 0; o >>= 1) v += __shfl_xor_sync(0xffffffffu, v, o);
    int w = threadIdx.x >> 5;
    if ((threadIdx.x & 31) == 0) sh[w] = v;
    __syncthreads();
    float t = 0.f;
#pragma unroll
    for (int i = 0; i < 8; i++) t += sh[i];
    __syncthreads();
    return t;
}

__device__ __forceinline__ float blk_max(float v, float* sh) {
#pragma unroll
    for (int o = 16; o > 0; o >>= 1) v = fmaxf(v, __shfl_xor_sync(0xffffffffu, v, o));
    int w = threadIdx.x >> 5;
    if ((threadIdx.x & 31) == 0) sh[w] = v;
    __syncthreads();
    float t = sh[0];
#pragma unroll
    for (int i = 1; i < 8; i++) t = fmaxf(t, sh[i]);
    __syncthreads();
    return t;
}

// ---------------- softmax over each score row (S_=2048 cols) ----------------
__global__ __launch_bounds__(256)
void softmax_kernel()
{
    __shared__ float sh[8];
    const long row = blockIdx.x;                   // 0..NTOK-1; g_sc is [NTOK][S_]
    float* sr = g_sc + row * (long)S_;
    const int tid = threadIdx.x;

    float v[8];
    float m = -1e30f;
#pragma unroll
    for (int k = 0; k < 8; k++) { v[k] = sr[tid + k * 256]; m = fmaxf(m, v[k]); }
    m = blk_max(m, sh);

    float s = 0.f;
#pragma unroll
    for (int k = 0; k < 8; k++) { v[k] = __expf(v[k] - m); s += v[k]; }
    s = blk_sum(s, sh);

    const float inv = 1.f / s;
#pragma unroll
    for (int k = 0; k < 8; k++) sr[tid + k * 256] = v[k] * inv;
}

// ---------------- LN1 (x + att) -> x1, and qf = cos(x1[:, :NQ] + theta_ry) ----------------
__global__ __launch_bounds__(256)
void ln1_qf_kernel(const float* __restrict__ x, const float* __restrict__ g,
                   const float* __restrict__ be, const float* __restrict__ th_ry)
{
    __shared__ float sh[8];
    const long row = blockIdx.x;
    const int tid = threadIdx.x;
    const float* xr = x     + row * (long)E_;
    const float* ar = g_att + row * (long)E_;

    float v[3]; float s = 0.f;
#pragma unroll
    for (int k = 0; k < 3; k++) { int j = tid + 256 * k; v[k] = xr[j] + ar[j]; s += v[k]; }
    float mean = blk_sum(s, sh) * (1.0f / 768.0f);

    float q = 0.f;
#pragma unroll
    for (int k = 0; k < 3; k++) { float d = v[k] - mean; q += d * d; }
    float rstd = rsqrtf(blk_sum(q, sh) * (1.0f / 768.0f) + 1e-5f);

#pragma unroll
    for (int k = 0; k < 3; k++) {
        int j = tid + 256 * k;
        float y = (v[k] - mean) * rstd * g[j] + be[j];
        g_x1[row * (long)E_ + j] = y;
        if (j < NQ_) g_qf[row * (long)NQ_ + j] = cosf(y + th_ry[j]);
    }
}

// ---------------- LN2 (x1 + ffn) -> out ----------------
__global__ __launch_bounds__(256)
void ln2_kernel(const float* __restrict__ g, const float* __restrict__ be,
                float* __restrict__ out)
{
    __shared__ float sh[8];
    const long row = blockIdx.x;
    const int tid = threadIdx.x;
    const float* xr = g_x1  + row * (long)E_;
    const float* fr = g_ffn + row * (long)E_;

    float v[3]; float s = 0.f;
#pragma unroll
    for (int k = 0; k < 3; k++) { int j = tid + 256 * k; v[k] = xr[j] + fr[j]; s += v[k]; }
    float mean = blk_sum(s, sh) * (1.0f / 768.0f);

    float q = 0.f;
#pragma unroll
    for (int k = 0; k < 3; k++) { float d = v[k] - mean; q += d * d; }
    float rstd = rsqrtf(blk_sum(q, sh) * (1.0f / 768.0f) + 1e-5f);

#pragma unroll
    for (int k = 0; k < 3; k++) {
        int j = tid + 256 * k;
        out[row * (long)E_ + j] = (v[k] - mean) * rstd * g[j] + be[j];
    }
}

// ---------------- launch ----------------
extern "C" void kernel_launch(void* const* d_in, const int* in_sizes, int n_in,
                              void* d_out, int out_size)
{
    (void)in_sizes; (void)n_in; (void)out_size;
    const float* x     = (const float*)d_in[0];
    const float* Wp    = (const float*)d_in[1];
    const float* th_rx = (const float*)d_in[2];
    const float* th_ry = (const float*)d_in[3];
    const float* W1    = (const float*)d_in[4];
    const float* b1    = (const float*)d_in[5];
    const float* W2    = (const float*)d_in[6];
    const float* b2    = (const float*)d_in[7];
    const float* g1    = (const float*)d_in[8];
    const float* be1   = (const float*)d_in[9];
    const float* g2    = (const float*)d_in[10];
    const float* be2   = (const float*)d_in[11];
    float* out = (float*)d_out;

    void *p;
    cudaGetSymbolAddress(&p, g_qa);  float* qa  = (float*)p;
    cudaGetSymbolAddress(&p, g_qaT); float* qaT = (float*)p;
    cudaGetSymbolAddress(&p, g_sc);  float* sc  = (float*)p;
    cudaGetSymbolAddress(&p, g_att); float* att = (float*)p;
    cudaGetSymbolAddress(&p, g_qf);  float* qf  = (float*)p;
    cudaGetSymbolAddress(&p, g_h);   float* h   = (float*)p;
    cudaGetSymbolAddress(&p, g_ffn); float* ffn = (float*)p;

    dim3 blk(256);

    // 1) proj + cos -> qa (and qaT)
    gemm_tf32<EPI_QA><<<dim3(E_ / 128, NTOK / 128, 1), blk>>>(
        x, Wp, qa, E_, E_, E_, E_, 0, 0, 0, th_rx);

    // 2) scores = qa qa^T / sqrt(8), batched over 8
    gemm_tf32<EPI_SCORES><<<dim3(S_ / 128, S_ / 128, B_), blk>>>(
        qa, qa, sc, E_, E_, E_, S_,
        (long)S_ * E_, (long)S_ * E_, (long)S_ * S_, nullptr);

    // 3) softmax rows
    softmax_kernel<<<NTOK, blk>>>();

    // 4) attn_out = P @ qa (B-operand = qaT [e][s])
    gemm_tf32<EPI_NONE><<<dim3(E_ / 128, S_ / 128, B_), blk>>>(
        sc, qaT, att, S_, S_, S_, E_,
        (long)S_ * S_, (long)E_ * S_, (long)S_ * E_, nullptr);

    // 5) x1 = LN(x + att); qf = cos(x1[:, :NQ] + theta_ry)
    ln1_qf_kernel<<<NTOK, blk>>>(x, g1, be1, th_ry);

    // 6) h = relu(qf @ W1^T + b1)
    gemm_tf32<EPI_RELU><<<dim3(FF_ / 128, NTOK / 128, 1), blk>>>(
        qf, W1, h, NQ_, NQ_, NQ_, FF_, 0, 0, 0, b1);

    // 7) ffn = h @ W2^T + b2
    gemm_tf32<EPI_BIAS><<<dim3(E_ / 128, NTOK / 128, 1), blk>>>(
        h, W2, ffn, FF_, FF_, FF_, E_, 0, 0, 0, b2);

    // 8) out = LN(x1 + ffn)
    ln2_kernel<<<NTOK, blk>>>(g2, be2, out);
}